// round 13
// baseline (speedup 1.0000x reference)
#include <cuda_runtime.h>
#include <cuda_bf16.h>
#include <cuda_fp16.h>
#include <cstdint>

// Problem constants
#define BATCH 4
#define CIN   256
#define COCT  32          // CIN/8 channel-octs
#define COUT  256
#define HH    64
#define WW    64
#define HW    4096
#define NTAP  9
#define KTOT  2304        // tap-major: k = tap*256 + c
#define NCH2  18          // merged chunks: 9 taps * 2 chunks of 128 channels

// ---------------- scratch ----------------
__device__ int4     g_idx[BATCH * NTAP * HW];
__device__ float4   g_wt [BATCH * NTAP * HW];
__device__ __half   g_bf[COUT * KTOT];          // w_conv fp16 [n][k]
__device__ __half   g_of[32 * KTOT];            // w_off fp16 [n(27->32)][k]
__device__ uint4    g_x8[BATCH * COCT * HW];    // x as 8-channel fp16 octs [b][c8][p]

// ---------------- helpers ----------------
__device__ __forceinline__ uint32_t smem_u32(const void* p) {
    uint32_t a;
    asm("{ .reg .u64 t; cvta.to.shared.u64 t, %1; cvt.u32.u64 %0, t; }" : "=r"(a) : "l"(p));
    return a;
}
__device__ __forceinline__ void ldm_x4(uint32_t* r, uint32_t addr) {
    asm volatile("ldmatrix.sync.aligned.m8n8.x4.shared.b16 {%0,%1,%2,%3}, [%4];"
                 : "=r"(r[0]), "=r"(r[1]), "=r"(r[2]), "=r"(r[3]) : "r"(addr));
}
__device__ __forceinline__ void mma_fp16(float* c, const uint32_t* a, const uint32_t* b) {
    asm volatile(
        "mma.sync.aligned.m16n8k16.row.col.f32.f16.f16.f32 "
        "{%0,%1,%2,%3}, {%4,%5,%6,%7}, {%8,%9}, {%0,%1,%2,%3};"
        : "+f"(c[0]), "+f"(c[1]), "+f"(c[2]), "+f"(c[3])
        : "r"(a[0]), "r"(a[1]), "r"(a[2]), "r"(a[3]), "r"(b[0]), "r"(b[1]));
}
__device__ __forceinline__ void cpasync16(uint32_t dst, const void* src) {
    asm volatile("cp.async.cg.shared.global [%0], [%1], 16;" :: "r"(dst), "l"(src));
}
#define CP_COMMIT() asm volatile("cp.async.commit_group;")
#define CP_WAIT0()  asm volatile("cp.async.wait_group 0;" ::: "memory")

__device__ __forceinline__ uint32_t pack_f16x2_single(float v0, float v1) {
    const __half h0 = __float2half_rn(v0);
    const __half h1 = __float2half_rn(v1);
    return (uint32_t)__half_as_ushort(h0) | ((uint32_t)__half_as_ushort(h1) << 16);
}
__device__ __forceinline__ void sts128(uint32_t addr, uint32_t r0, uint32_t r1,
                                       uint32_t r2, uint32_t r3) {
    asm volatile("st.shared.v4.b32 [%0], {%1, %2, %3, %4};"
                 :: "r"(addr), "r"(r0), "r"(r1), "r"(r2), "r"(r3) : "memory");
}

// ---------------------------------------------------------------------------
// Stage 0 (merged): prepack weights (fp16, tap-major) + x (fp16 channel octs)
// ---------------------------------------------------------------------------
#define NPRE1 ((COUT + 32) * KTOT)            // 663552
#define NPRE2 (BATCH * COCT * HW)             // 524288

__global__ __launch_bounds__(256)
void prepack_kernel(const float* __restrict__ w_conv,
                    const float* __restrict__ w_off,
                    const float* __restrict__ x)
{
    const int i = blockIdx.x * 256 + threadIdx.x;
    if (i < COUT * KTOT) {
        const int n = i / KTOT, k = i % KTOT;
        const int tap = k >> 8, c = k & 255;
        g_bf[i] = __float2half_rn(w_conv[(n * CIN + c) * 9 + tap]);
    } else if (i < NPRE1) {
        const int j = i - COUT * KTOT;
        const int n = j / KTOT, k = j % KTOT;
        const int tap = k >> 8, c = k & 255;
        g_of[j] = __float2half_rn((n < 27) ? w_off[(n * CIN + c) * 9 + tap] : 0.f);
    } else {
        const int j = i - NPRE1;
        if (j < NPRE2) {
            const int b  = j >> 17;           // / (COCT*HW)
            const int r  = j & 131071;
            const int c8 = r >> 12;
            const int p  = r & 4095;
            const float* xp = x + ((size_t)b * CIN + 8 * c8) * HW + p;
            uint4 q;
            q.x = pack_f16x2_single(xp[0],      xp[HW]);
            q.y = pack_f16x2_single(xp[2 * HW], xp[3 * HW]);
            q.z = pack_f16x2_single(xp[4 * HW], xp[5 * HW]);
            q.w = pack_f16x2_single(xp[6 * HW], xp[7 * HW]);
            g_x8[j] = q;
        }
    }
}

// ---------------------------------------------------------------------------
// Fused kernel: 128 CTAs x 512 threads, CTA = 128 pixels x 256 n.
// Phase 1 = offset conv (fp16 mma, N=32); phase 2 = main GEMM (N=256).
// K-chunks of 128 channels (one tap), 18 chunks, double-buffered.
// Gathers use LDG.128 channel octs; one oct-group in flight (16 regs).
// ---------------------------------------------------------------------------
// Phase-1 smem
#define OROWB  272
#define OS_A   0
#define OS_B   (128 * OROWB)                  // 34816
#define OBUF   (OS_B + 32 * OROWB)            // 43520
#define OS_ACC (2 * OBUF)                     // 87040
// Phase-2 smem
#define ROWB   272
#define SM_A   0
#define SM_B   (128 * ROWB)                   // 34816
#define BUF_BYTES (SM_B + 256 * ROWB)         // 104448
#define SMEM_TOTAL (2 * BUF_BYTES)            // 208896

__global__ __launch_bounds__(512, 1)
void fused_kernel(const float* __restrict__ b_off,
                  float* __restrict__ out)
{
    extern __shared__ char smem[];
    const uint32_t sb = smem_u32(smem);
    const int t    = threadIdx.x;
    const int lane = t & 31;
    const int wid  = t >> 5;
    const int b    = blockIdx.x >> 5;
    const int p0   = (blockIdx.x & 31) * 128;

    const uint4* xob = g_x8 + (size_t)b * COCT * HW;

    const int am = t & 127;   // pixel
    const int aq = t >> 7;    // channel quarter: owns 4 octs (32 ch) of chunk

    //======================= PHASE 1: offset conv =======================
    {
        const int ph = (p0 + am) >> 6;
        const int pw = (p0 + am) & 63;

        const int mw = wid & 7;
        const int nw = wid >> 3;

        const uint32_t a_row  = (uint32_t)(mw * 16 + (lane & 15));
        const uint32_t a_colb = (uint32_t)((lane >> 4) * 16);
        const uint32_t b_row  = (uint32_t)(nw * 16 + (lane & 7) + ((lane >> 4) << 3));
        const uint32_t b_colb = (uint32_t)(((lane >> 3) & 1) * 16);

        float acc[2][4];
#pragma unroll
        for (int ni = 0; ni < 2; ni++)
#pragma unroll
            for (int j = 0; j < 4; j++) acc[ni][j] = 0.f;

        const uint4* xcn = xob;
        bool okn = false;
        uint32_t nbase = sb;

        auto set_meta = [&](int chunk, uint32_t base) {
            const int tap = chunk >> 1;
            const int co0 = (chunk & 1) * 16;     // oct offset of 128-ch chunk
            const int yy = ph - 1 + tap / 3;
            const int xx = pw - 1 + tap % 3;
            okn = (yy >= 0) && (yy < HH) && (xx >= 0) && (xx < WW);
            xcn = xob + (size_t)(co0 + aq * 4) * HW + (okn ? (yy * WW + xx) : 0);
            nbase = base;
        };
        auto a_load1 = [&](int g, uint4* v) {
            if (okn) *v = __ldg(xcn + (size_t)g * HW);
            else     *v = make_uint4(0u, 0u, 0u, 0u);
        };
        auto a_finish = [&](int g, const uint4* v) {
            const uint32_t colb = (uint32_t)(64 * aq + 16 * g);
            sts128(nbase + OS_A + (uint32_t)am * OROWB + colb,
                   v->x, v->y, v->z, v->w);
        };
        auto b_async = [&](int chunk, uint32_t base) {
            const int tap = chunk >> 1;
            const int c0  = (chunk & 1) * 128;
            const int n = t >> 4, vw = t & 15;
            const size_t gofs = (size_t)n * KTOT + tap * 256 + c0 + vw * 8;
            cpasync16(base + OS_B + (uint32_t)(n * OROWB + vw * 16), g_of + gofs);
            CP_COMMIT();
        };
        auto pass_step = [&](uint32_t base, int s) {
            uint32_t bf[2][2];
            {
                uint32_t r[4];
                ldm_x4(r, base + OS_B + b_row * OROWB + b_colb + s * 32);
                bf[0][0] = r[0]; bf[0][1] = r[1];
                bf[1][0] = r[2]; bf[1][1] = r[3];
            }
            uint32_t af[4];
            ldm_x4(af, base + OS_A + a_row * OROWB + a_colb + s * 32);
#pragma unroll
            for (int ni = 0; ni < 2; ni++)
                mma_fp16(acc[ni], af, bf[ni]);
        };

        // prologue
        b_async(0, sb);
        set_meta(0, sb);
        {
            uint4 u;
#pragma unroll
            for (int g = 0; g < 4; g++) { a_load1(g, &u); a_finish(g, &u); }
        }
        CP_WAIT0();
        __syncthreads();

        for (int chunk = 0; chunk < NCH2; chunk++) {
            const uint32_t cur = sb + (uint32_t)(chunk & 1) * OBUF;
            const bool hn = (chunk + 1 < NCH2);
            uint4 v;
            if (hn) {
                const uint32_t nxt = sb + (uint32_t)((chunk + 1) & 1) * OBUF;
                b_async(chunk + 1, nxt);
                set_meta(chunk + 1, nxt);
                a_load1(0, &v);
            }
            pass_step(cur, 0);
            pass_step(cur, 1);
            if (hn) { a_finish(0, &v); a_load1(1, &v); }
            pass_step(cur, 2);
            pass_step(cur, 3);
            if (hn) { a_finish(1, &v); a_load1(2, &v); }
            pass_step(cur, 4);
            pass_step(cur, 5);
            if (hn) { a_finish(2, &v); a_load1(3, &v); }
            pass_step(cur, 6);
            pass_step(cur, 7);
            if (hn) { a_finish(3, &v); }
            if (hn) CP_WAIT0();
            __syncthreads();
        }

        // stash acc so each thread reads one pixel's 27 outputs
        float* sacc = reinterpret_cast<float*>(smem + OS_ACC);
        const int mb = mw * 16 + (lane >> 2);
        const int nb = nw * 16 + (lane & 3) * 2;
#pragma unroll
        for (int ni = 0; ni < 2; ni++) {
            const int n = nb + ni * 8;
            sacc[mb * 33 + n]           = acc[ni][0];
            sacc[mb * 33 + n + 1]       = acc[ni][1];
            sacc[(mb + 8) * 33 + n]     = acc[ni][2];
            sacc[(mb + 8) * 33 + n + 1] = acc[ni][3];
        }
        __syncthreads();

        if (t < 128) {
            const int p = p0 + t;
            const int h = p >> 6, w = p & 63;
            const float* row = sacc + t * 33;
#pragma unroll
            for (int k = 0; k < NTAP; k++) {
                const float dy = row[2 * k]     + __ldg(b_off + 2 * k);
                const float dx = row[2 * k + 1] + __ldg(b_off + 2 * k + 1);
                const float mz = row[18 + k]    + __ldg(b_off + 18 + k);
                const float m  = 1.f / (1.f + expf(-mz));

                const float py = dy + (float)(h - 1 + k / 3);
                const float px = dx + (float)(w - 1 + k % 3);
                const float y0 = floorf(py);
                const float x0 = floorf(px);
                const float wy = py - y0;
                const float wx = px - x0;

                const float cy[2]  = { y0, y0 + 1.f };
                const float cx[2]  = { x0, x0 + 1.f };
                const float wyv[2] = { 1.f - wy, wy };
                const float wxv[2] = { 1.f - wx, wx };

                int   idxv[4];
                float wtv[4];
#pragma unroll
                for (int jy = 0; jy < 2; jy++) {
#pragma unroll
                    for (int jx = 0; jx < 2; jx++) {
                        const float yc = cy[jy], xc = cx[jx];
                        const bool valid = (yc >= 0.f) && (yc <= (float)(HH - 1)) &&
                                           (xc >= 0.f) && (xc <= (float)(WW - 1));
                        const int yi = (int)fminf(fmaxf(yc, 0.f), (float)(HH - 1));
                        const int xi = (int)fminf(fmaxf(xc, 0.f), (float)(WW - 1));
                        const int j = jy * 2 + jx;
                        idxv[j] = yi * WW + xi;
                        wtv[j]  = valid ? (wyv[jy] * wxv[jx] * m) : 0.f;
                    }
                }
                const int o = (b * NTAP + k) * HW + p;
                g_idx[o] = make_int4(idxv[0], idxv[1], idxv[2], idxv[3]);
                g_wt[o]  = make_float4(wtv[0], wtv[1], wtv[2], wtv[3]);
            }
        }
    }
    __syncthreads();   // meta written (global, same CTA) + smem free

    //======================= PHASE 2: main GEMM =======================
    {
        const int mw = wid & 1;
        const int nw = wid >> 1;

        float acc[4][4][4];
#pragma unroll
        for (int mi = 0; mi < 4; mi++)
#pragma unroll
            for (int ni = 0; ni < 4; ni++)
#pragma unroll
                for (int j = 0; j < 4; j++) acc[mi][ni][j] = 0.f;

        const uint32_t a_row  = (uint32_t)(mw * 64 + (lane & 15));
        const uint32_t a_colb = (uint32_t)((lane >> 4) * 16);
        const uint32_t b_row  = (uint32_t)(nw * 32 + (lane & 7) + ((lane >> 4) << 3));
        const uint32_t b_colb = (uint32_t)(((lane >> 3) & 1) * 16);

        int4   idn;
        float4 wtn;
        const uint4* xcn = xob;
        uint32_t nbase = sb;

        auto set_meta = [&](int chunk, uint32_t base, bool reload) {
            const int tap = chunk >> 1;
            const int co0 = (chunk & 1) * 16;
            if (reload) {
                const int off = (b * NTAP + tap) * HW + p0 + am;
                idn = g_idx[off];
                wtn = g_wt[off];
            }
            xcn = xob + (size_t)(co0 + aq * 4) * HW;
            nbase = base;
        };
        auto a_load4 = [&](int g, uint4* v) {
            const uint4* xp = xcn + (size_t)g * HW;
            v[0] = __ldg(xp + idn.x); v[1] = __ldg(xp + idn.y);
            v[2] = __ldg(xp + idn.z); v[3] = __ldg(xp + idn.w);
        };
        auto dotpack_w = [&](uint32_t c0, uint32_t c1, uint32_t c2, uint32_t c3) -> uint32_t {
            const float2 f0 = __half22float2(*reinterpret_cast<const __half2*>(&c0));
            const float2 f1 = __half22float2(*reinterpret_cast<const __half2*>(&c1));
            const float2 f2 = __half22float2(*reinterpret_cast<const __half2*>(&c2));
            const float2 f3 = __half22float2(*reinterpret_cast<const __half2*>(&c3));
            const float a0 = wtn.x * f0.x + wtn.y * f1.x + wtn.z * f2.x + wtn.w * f3.x;
            const float a1 = wtn.x * f0.y + wtn.y * f1.y + wtn.z * f2.y + wtn.w * f3.y;
            return pack_f16x2_single(a0, a1);
        };
        auto a_finish = [&](int g, const uint4* v) {
            const uint32_t w0 = dotpack_w(v[0].x, v[1].x, v[2].x, v[3].x);
            const uint32_t w1 = dotpack_w(v[0].y, v[1].y, v[2].y, v[3].y);
            const uint32_t w2 = dotpack_w(v[0].z, v[1].z, v[2].z, v[3].z);
            const uint32_t w3 = dotpack_w(v[0].w, v[1].w, v[2].w, v[3].w);
            const uint32_t colb = (uint32_t)(64 * aq + 16 * g);
            sts128(nbase + SM_A + (uint32_t)am * ROWB + colb, w0, w1, w2, w3);
        };
        auto b_async = [&](int chunk, uint32_t base) {
            const int tap = chunk >> 1;
            const int c0  = (chunk & 1) * 128;
#pragma unroll
            for (int q2 = 0; q2 < 8; q2++) {
                const int v2 = t + 512 * q2;
                const int n = v2 >> 4, vw = v2 & 15;
                const size_t gofs = (size_t)n * KTOT + tap * 256 + c0 + vw * 8;
                cpasync16(base + SM_B + (uint32_t)(n * ROWB + vw * 16), g_bf + gofs);
            }
            CP_COMMIT();
        };
        auto pass_step = [&](uint32_t base, int s) {
            const uint32_t A = base + SM_A;
            const uint32_t B = base + SM_B;
            uint32_t bf[4][2];
#pragma unroll
            for (int np = 0; np < 2; np++) {
                uint32_t r[4];
                ldm_x4(r, B + (b_row + np * 16) * ROWB + b_colb + s * 32);
                bf[np * 2][0] = r[0]; bf[np * 2][1] = r[1];
                bf[np * 2 + 1][0] = r[2]; bf[np * 2 + 1][1] = r[3];
            }
#pragma unroll
            for (int mi = 0; mi < 4; mi++) {
                uint32_t af[4];
                ldm_x4(af, A + (a_row + mi * 16) * ROWB + a_colb + s * 32);
#pragma unroll
                for (int ni = 0; ni < 4; ni++)
                    mma_fp16(acc[mi][ni], af, bf[ni]);
            }
        };

        // prologue
        b_async(0, sb);
        set_meta(0, sb, true);
        {
            uint4 u[4];
#pragma unroll
            for (int g = 0; g < 4; g++) { a_load4(g, u); a_finish(g, u); }
        }
        CP_WAIT0();
        __syncthreads();

        for (int chunk = 0; chunk < NCH2; chunk++) {
            const uint32_t cur = sb + (uint32_t)(chunk & 1) * BUF_BYTES;
            const bool hn = (chunk + 1 < NCH2);
            uint4 v[4];
            if (hn) {
                const uint32_t nxt = sb + (uint32_t)((chunk + 1) & 1) * BUF_BYTES;
                b_async(chunk + 1, nxt);
                set_meta(chunk + 1, nxt, (((chunk + 1) & 1) == 0));
                a_load4(0, v);
            }
            pass_step(cur, 0);
            pass_step(cur, 1);
            if (hn) { a_finish(0, v); a_load4(1, v); }
            pass_step(cur, 2);
            pass_step(cur, 3);
            if (hn) { a_finish(1, v); a_load4(2, v); }
            pass_step(cur, 4);
            pass_step(cur, 5);
            if (hn) { a_finish(2, v); a_load4(3, v); }
            pass_step(cur, 6);
            pass_step(cur, 7);
            if (hn) { a_finish(3, v); }
            if (hn) CP_WAIT0();
            __syncthreads();
        }

        // epilogue
        float* ob = out + (size_t)b * COUT * HW + p0;
        const int mbase = mw * 64 + (lane >> 2);
        const int nbase2 = nw * 32 + (lane & 3) * 2;
#pragma unroll
        for (int mi = 0; mi < 4; mi++) {
#pragma unroll
            for (int ni = 0; ni < 4; ni++) {
                const int m = mbase + mi * 16;
                const int n = nbase2 + ni * 8;
                ob[(size_t)n * HW + m]           = acc[mi][ni][0];
                ob[(size_t)(n + 1) * HW + m]     = acc[mi][ni][1];
                ob[(size_t)n * HW + m + 8]       = acc[mi][ni][2];
                ob[(size_t)(n + 1) * HW + m + 8] = acc[mi][ni][3];
            }
        }
    }
}

// ---------------------------------------------------------------------------
extern "C" void kernel_launch(void* const* d_in, const int* in_sizes, int n_in,
                              void* d_out, int out_size)
{
    (void)in_sizes; (void)n_in; (void)out_size;
    const float* x      = (const float*)d_in[0];
    const float* w_off  = (const float*)d_in[1];
    const float* b_off  = (const float*)d_in[2];
    const float* w_conv = (const float*)d_in[3];
    float* out = (float*)d_out;

    cudaFuncSetAttribute(fused_kernel,
                         cudaFuncAttributeMaxDynamicSharedMemorySize, SMEM_TOTAL);

    prepack_kernel<<<(NPRE1 + NPRE2 + 255) / 256, 256>>>(w_conv, w_off, x);
    fused_kernel<<<128, 512, SMEM_TOTAL>>>(b_off, out);
}

// round 14
// speedup vs baseline: 1.0161x; 1.0161x over previous
#include <cuda_runtime.h>
#include <cuda_bf16.h>
#include <cuda_fp16.h>
#include <cstdint>

// Problem constants
#define BATCH 4
#define CIN   256
#define CQUAD 64          // CIN/4 channel-quads
#define COUT  256
#define HH    64
#define WW    64
#define HW    4096
#define NTAP  9
#define KTOT  2304        // tap-major: k = tap*256 + c
#define NCH2  18          // phase-2 chunks: 9 taps * 2 chunks of 128 channels

// ---------------- scratch ----------------
__device__ int4     g_idx[BATCH * NTAP * HW];
__device__ float4   g_wt [BATCH * NTAP * HW];
__device__ __half   g_bf[COUT * KTOT];          // w_conv fp16 [n][k]
__device__ __half   g_of[32 * KTOT];            // w_off fp16 [n(27->32)][k]
__device__ uint2    g_x4[BATCH * CQUAD * HW];   // x as 4-channel fp16 quads [b][c4][p]

// ---------------- helpers ----------------
__device__ __forceinline__ uint32_t smem_u32(const void* p) {
    uint32_t a;
    asm("{ .reg .u64 t; cvta.to.shared.u64 t, %1; cvt.u32.u64 %0, t; }" : "=r"(a) : "l"(p));
    return a;
}
__device__ __forceinline__ void ldm_x4(uint32_t* r, uint32_t addr) {
    asm volatile("ldmatrix.sync.aligned.m8n8.x4.shared.b16 {%0,%1,%2,%3}, [%4];"
                 : "=r"(r[0]), "=r"(r[1]), "=r"(r[2]), "=r"(r[3]) : "r"(addr));
}
__device__ __forceinline__ void mma_fp16(float* c, const uint32_t* a, const uint32_t* b) {
    asm volatile(
        "mma.sync.aligned.m16n8k16.row.col.f32.f16.f16.f32 "
        "{%0,%1,%2,%3}, {%4,%5,%6,%7}, {%8,%9}, {%0,%1,%2,%3};"
        : "+f"(c[0]), "+f"(c[1]), "+f"(c[2]), "+f"(c[3])
        : "r"(a[0]), "r"(a[1]), "r"(a[2]), "r"(a[3]), "r"(b[0]), "r"(b[1]));
}
__device__ __forceinline__ void cpasync16(uint32_t dst, const void* src) {
    asm volatile("cp.async.cg.shared.global [%0], [%1], 16;" :: "r"(dst), "l"(src));
}
#define CP_COMMIT() asm volatile("cp.async.commit_group;")
#define CP_WAIT0()  asm volatile("cp.async.wait_group 0;" ::: "memory")

__device__ __forceinline__ uint32_t pack_f16x2_single(float v0, float v1) {
    const __half h0 = __float2half_rn(v0);
    const __half h1 = __float2half_rn(v1);
    return (uint32_t)__half_as_ushort(h0) | ((uint32_t)__half_as_ushort(h1) << 16);
}
__device__ __forceinline__ void sts128(uint32_t addr, uint32_t r0, uint32_t r1,
                                       uint32_t r2, uint32_t r3) {
    asm volatile("st.shared.v4.b32 [%0], {%1, %2, %3, %4};"
                 :: "r"(addr), "r"(r0), "r"(r1), "r"(r2), "r"(r3) : "memory");
}

// ---------------------------------------------------------------------------
// Stage 0 (merged): prepack weights (fp16, tap-major) + x (fp16 channel quads)
// ---------------------------------------------------------------------------
#define NPRE1 ((COUT + 32) * KTOT)            // 663552
#define NPRE2 (BATCH * CQUAD * HW)            // 1048576

__global__ __launch_bounds__(256)
void prepack_kernel(const float* __restrict__ w_conv,
                    const float* __restrict__ w_off,
                    const float* __restrict__ x)
{
    const int i = blockIdx.x * 256 + threadIdx.x;
    if (i < COUT * KTOT) {
        const int n = i / KTOT, k = i % KTOT;
        const int tap = k >> 8, c = k & 255;
        g_bf[i] = __float2half_rn(w_conv[(n * CIN + c) * 9 + tap]);
    } else if (i < NPRE1) {
        const int j = i - COUT * KTOT;
        const int n = j / KTOT, k = j % KTOT;
        const int tap = k >> 8, c = k & 255;
        g_of[j] = __float2half_rn((n < 27) ? w_off[(n * CIN + c) * 9 + tap] : 0.f);
    } else {
        const int j = i - NPRE1;
        if (j < NPRE2) {
            const int b  = j >> 18;           // / (CQUAD*HW)
            const int r  = j & 262143;
            const int c4 = r >> 12;
            const int p  = r & 4095;
            const float* xp = x + ((size_t)b * CIN + 4 * c4) * HW + p;
            uint2 q;
            q.x = pack_f16x2_single(xp[0], xp[HW]);
            q.y = pack_f16x2_single(xp[2 * HW], xp[3 * HW]);
            g_x4[j] = q;
        }
    }
}

// ---------------------------------------------------------------------------
// Fused kernel: 128 CTAs x 512 threads, CTA = 128 pixels x 256 n.
// Phase 1 = offset conv (fp16 mma, N=32), 9 chunks of 256 channels (1 tap).
// Phase 2 = main GEMM (N=256), 18 chunks of 128 channels, double-buffered.
// ---------------------------------------------------------------------------
// Phase-1 smem (K=256 chunks)
#define OROWB  528
#define OS_A   0
#define OS_B   (128 * OROWB)                  // 67584
#define OBUF   (OS_B + 32 * OROWB)            // 84480
#define OS_ACC (2 * OBUF)                     // 168960 (sacc 128*33*4 = 16896)
// Phase-2 smem (K=128 chunks)
#define ROWB   272
#define SM_A   0
#define SM_B   (128 * ROWB)                   // 34816
#define BUF_BYTES (SM_B + 256 * ROWB)         // 104448
#define SMEM_TOTAL (2 * BUF_BYTES)            // 208896

__global__ __launch_bounds__(512, 1)
void fused_kernel(const float* __restrict__ b_off,
                  float* __restrict__ out)
{
    extern __shared__ char smem[];
    const uint32_t sb = smem_u32(smem);
    const int t    = threadIdx.x;
    const int lane = t & 31;
    const int wid  = t >> 5;
    const int b    = blockIdx.x >> 5;
    const int p0   = (blockIdx.x & 31) * 128;

    const uint2* xqb = g_x4 + (size_t)b * CQUAD * HW;

    const int am = t & 127;   // pixel
    const int aq = t >> 7;    // channel quarter

    //============== PHASE 1: offset conv (9 chunks x 256 ch) ==============
    {
        const int ph = (p0 + am) >> 6;
        const int pw = (p0 + am) & 63;

        const int mw = wid & 7;
        const int nw = wid >> 3;

        const uint32_t a_row  = (uint32_t)(mw * 16 + (lane & 15));
        const uint32_t a_colb = (uint32_t)((lane >> 4) * 16);
        const uint32_t b_row  = (uint32_t)(nw * 16 + (lane & 7) + ((lane >> 4) << 3));
        const uint32_t b_colb = (uint32_t)(((lane >> 3) & 1) * 16);

        float acc[2][4];
#pragma unroll
        for (int ni = 0; ni < 2; ni++)
#pragma unroll
            for (int j = 0; j < 4; j++) acc[ni][j] = 0.f;

        const uint2* xcn = xqb;
        bool okn = false;
        uint32_t nbase = sb;

        // each thread owns 64 channels = 16 quads of the 256-ch chunk
        auto set_meta = [&](int tap, uint32_t base) {
            const int yy = ph - 1 + tap / 3;
            const int xx = pw - 1 + tap % 3;
            okn = (yy >= 0) && (yy < HH) && (xx >= 0) && (xx < WW);
            xcn = xqb + (size_t)(aq * 16) * HW + (okn ? (yy * WW + xx) : 0);
            nbase = base;
        };
        auto a_load1 = [&](int g, uint2* v) {
            if (okn) *v = __ldg(xcn + (size_t)g * HW);
            else     *v = make_uint2(0u, 0u);
        };
        auto a_finish2 = [&](int j, const uint2* v0, const uint2* v1) {
            // quads 2j,2j+1 -> bytes 128*aq + 16*j
            const uint32_t colb = (uint32_t)(128 * aq + 16 * j);
            sts128(nbase + OS_A + (uint32_t)am * OROWB + colb,
                   v0->x, v0->y, v1->x, v1->y);
        };
        auto b_async = [&](int tap, uint32_t base) {
            // B tile: 32 n x 256 ch x 2B = 16 KB = 1024 vec16; 2 per thread
            const int n = t >> 4, vw = t & 15;
            const size_t gofs = (size_t)n * KTOT + tap * 256 + vw * 8;
            const uint32_t bo = (uint32_t)(n * OROWB + vw * 16);
            cpasync16(base + OS_B + bo, g_of + gofs);
            cpasync16(base + OS_B + bo + 256, g_of + gofs + 128);
            CP_COMMIT();
        };
        auto pass_step = [&](uint32_t base, int s) {
            uint32_t bf[2][2];
            {
                uint32_t r[4];
                ldm_x4(r, base + OS_B + b_row * OROWB + b_colb + s * 32);
                bf[0][0] = r[0]; bf[0][1] = r[1];
                bf[1][0] = r[2]; bf[1][1] = r[3];
            }
            uint32_t af[4];
            ldm_x4(af, base + OS_A + a_row * OROWB + a_colb + s * 32);
#pragma unroll
            for (int ni = 0; ni < 2; ni++)
                mma_fp16(acc[ni], af, bf[ni]);
        };

        // prologue: build chunk 0 (tap 0)
        b_async(0, sb);
        set_meta(0, sb);
        {
            uint2 u0, u1;
#pragma unroll
            for (int j = 0; j < 8; j++) {
                a_load1(2 * j, &u0); a_load1(2 * j + 1, &u1);
                a_finish2(j, &u0, &u1);
            }
        }
        CP_WAIT0();
        __syncthreads();

        for (int chunk = 0; chunk < NTAP; chunk++) {
            const uint32_t cur = sb + (uint32_t)(chunk & 1) * OBUF;
            const bool hn = (chunk + 1 < NTAP);
            uint2 v0, v1;
            if (hn) {
                const uint32_t nxt = sb + (uint32_t)((chunk + 1) & 1) * OBUF;
                b_async(chunk + 1, nxt);
                set_meta(chunk + 1, nxt);
                a_load1(0, &v0); a_load1(1, &v1);
            }
#pragma unroll
            for (int s = 0; s < 16; s++) {
                pass_step(cur, s);
                if (hn && (s & 1)) {
                    const int j = s >> 1;         // 0..7
                    a_finish2(j, &v0, &v1);
                    if (j < 7) { a_load1(2 * j + 2, &v0); a_load1(2 * j + 3, &v1); }
                }
            }
            if (hn) CP_WAIT0();
            __syncthreads();
        }

        // stash acc so each thread reads one pixel's 27 outputs
        float* sacc = reinterpret_cast<float*>(smem + OS_ACC);
        const int mb = mw * 16 + (lane >> 2);
        const int nb = nw * 16 + (lane & 3) * 2;
#pragma unroll
        for (int ni = 0; ni < 2; ni++) {
            const int n = nb + ni * 8;
            sacc[mb * 33 + n]           = acc[ni][0];
            sacc[mb * 33 + n + 1]       = acc[ni][1];
            sacc[(mb + 8) * 33 + n]     = acc[ni][2];
            sacc[(mb + 8) * 33 + n + 1] = acc[ni][3];
        }
        __syncthreads();

        if (t < 128) {
            const int p = p0 + t;
            const int h = p >> 6, w = p & 63;
            const float* row = sacc + t * 33;
#pragma unroll
            for (int k = 0; k < NTAP; k++) {
                const float dy = row[2 * k]     + __ldg(b_off + 2 * k);
                const float dx = row[2 * k + 1] + __ldg(b_off + 2 * k + 1);
                const float mz = row[18 + k]    + __ldg(b_off + 18 + k);
                const float m  = 1.f / (1.f + expf(-mz));

                const float py = dy + (float)(h - 1 + k / 3);
                const float px = dx + (float)(w - 1 + k % 3);
                const float y0 = floorf(py);
                const float x0 = floorf(px);
                const float wy = py - y0;
                const float wx = px - x0;

                const float cy[2]  = { y0, y0 + 1.f };
                const float cx[2]  = { x0, x0 + 1.f };
                const float wyv[2] = { 1.f - wy, wy };
                const float wxv[2] = { 1.f - wx, wx };

                int   idxv[4];
                float wtv[4];
#pragma unroll
                for (int jy = 0; jy < 2; jy++) {
#pragma unroll
                    for (int jx = 0; jx < 2; jx++) {
                        const float yc = cy[jy], xc = cx[jx];
                        const bool valid = (yc >= 0.f) && (yc <= (float)(HH - 1)) &&
                                           (xc >= 0.f) && (xc <= (float)(WW - 1));
                        const int yi = (int)fminf(fmaxf(yc, 0.f), (float)(HH - 1));
                        const int xi = (int)fminf(fmaxf(xc, 0.f), (float)(WW - 1));
                        const int j = jy * 2 + jx;
                        idxv[j] = yi * WW + xi;
                        wtv[j]  = valid ? (wyv[jy] * wxv[jx] * m) : 0.f;
                    }
                }
                const int o = (b * NTAP + k) * HW + p;
                g_idx[o] = make_int4(idxv[0], idxv[1], idxv[2], idxv[3]);
                g_wt[o]  = make_float4(wtv[0], wtv[1], wtv[2], wtv[3]);
            }
        }
    }
    __syncthreads();   // meta written (global, same CTA) + smem free

    //======================= PHASE 2: main GEMM =======================
    {
        const int mw = wid & 1;
        const int nw = wid >> 1;

        float acc[4][4][4];
#pragma unroll
        for (int mi = 0; mi < 4; mi++)
#pragma unroll
            for (int ni = 0; ni < 4; ni++)
#pragma unroll
                for (int j = 0; j < 4; j++) acc[mi][ni][j] = 0.f;

        const uint32_t a_row  = (uint32_t)(mw * 64 + (lane & 15));
        const uint32_t a_colb = (uint32_t)((lane >> 4) * 16);
        const uint32_t b_row  = (uint32_t)(nw * 32 + (lane & 7) + ((lane >> 4) << 3));
        const uint32_t b_colb = (uint32_t)(((lane >> 3) & 1) * 16);

        int4   idn;
        float4 wtn;
        const uint2* xcn = xqb;
        uint32_t nbase = sb;

        auto set_meta = [&](int chunk, uint32_t base, bool reload) {
            const int tap = chunk >> 1;
            const int cg0 = (chunk & 1) * 32;
            if (reload) {
                const int off = (b * NTAP + tap) * HW + p0 + am;
                idn = g_idx[off];
                wtn = g_wt[off];
            }
            xcn = xqb + (size_t)(cg0 + aq * 8) * HW;
            nbase = base;
        };
        auto a_load4 = [&](int g, uint2* v) {
            const uint2* xp = xcn + (size_t)g * HW;
            v[0] = __ldg(xp + idn.x); v[1] = __ldg(xp + idn.y);
            v[2] = __ldg(xp + idn.z); v[3] = __ldg(xp + idn.w);
        };
        auto dotpack2 = [&](const uint2* v, uint32_t* o) {
            const float2 f0a = __half22float2(*reinterpret_cast<const __half2*>(&v[0].x));
            const float2 f1a = __half22float2(*reinterpret_cast<const __half2*>(&v[1].x));
            const float2 f2a = __half22float2(*reinterpret_cast<const __half2*>(&v[2].x));
            const float2 f3a = __half22float2(*reinterpret_cast<const __half2*>(&v[3].x));
            const float a0 = wtn.x * f0a.x + wtn.y * f1a.x + wtn.z * f2a.x + wtn.w * f3a.x;
            const float a1 = wtn.x * f0a.y + wtn.y * f1a.y + wtn.z * f2a.y + wtn.w * f3a.y;
            o[0] = pack_f16x2_single(a0, a1);
            const float2 f0b = __half22float2(*reinterpret_cast<const __half2*>(&v[0].y));
            const float2 f1b = __half22float2(*reinterpret_cast<const __half2*>(&v[1].y));
            const float2 f2b = __half22float2(*reinterpret_cast<const __half2*>(&v[2].y));
            const float2 f3b = __half22float2(*reinterpret_cast<const __half2*>(&v[3].y));
            const float a2 = wtn.x * f0b.x + wtn.y * f1b.x + wtn.z * f2b.x + wtn.w * f3b.x;
            const float a3 = wtn.x * f0b.y + wtn.y * f1b.y + wtn.z * f2b.y + wtn.w * f3b.y;
            o[1] = pack_f16x2_single(a2, a3);
        };
        auto a_finish2 = [&](int j, const uint2* v0, const uint2* v1) {
            uint32_t w0[2], w1[2];
            dotpack2(v0, w0);
            dotpack2(v1, w1);
            const uint32_t colb = (uint32_t)(64 * aq + 16 * j);
            sts128(nbase + SM_A + (uint32_t)am * ROWB + colb,
                   w0[0], w0[1], w1[0], w1[1]);
        };
        auto b_async = [&](int chunk, uint32_t base) {
            const int tap = chunk >> 1;
            const int c0  = (chunk & 1) * 128;
#pragma unroll
            for (int q2 = 0; q2 < 8; q2++) {
                const int v2 = t + 512 * q2;
                const int n = v2 >> 4, vw = v2 & 15;
                const size_t gofs = (size_t)n * KTOT + tap * 256 + c0 + vw * 8;
                cpasync16(base + SM_B + (uint32_t)(n * ROWB + vw * 16), g_bf + gofs);
            }
            CP_COMMIT();
        };
        auto pass_step = [&](uint32_t base, int s) {
            const uint32_t A = base + SM_A;
            const uint32_t B = base + SM_B;
            uint32_t bf[4][2];
#pragma unroll
            for (int np = 0; np < 2; np++) {
                uint32_t r[4];
                ldm_x4(r, B + (b_row + np * 16) * ROWB + b_colb + s * 32);
                bf[np * 2][0] = r[0]; bf[np * 2][1] = r[1];
                bf[np * 2 + 1][0] = r[2]; bf[np * 2 + 1][1] = r[3];
            }
#pragma unroll
            for (int mi = 0; mi < 4; mi++) {
                uint32_t af[4];
                ldm_x4(af, A + (a_row + mi * 16) * ROWB + a_colb + s * 32);
#pragma unroll
                for (int ni = 0; ni < 4; ni++)
                    mma_fp16(acc[mi][ni], af, bf[ni]);
            }
        };

        // prologue
        b_async(0, sb);
        set_meta(0, sb, true);
        {
            uint2 u0[4], u1[4];
#pragma unroll
            for (int j = 0; j < 4; j++) {
                a_load4(2 * j, u0); a_load4(2 * j + 1, u1);
                a_finish2(j, u0, u1);
            }
        }
        CP_WAIT0();
        __syncthreads();

        for (int chunk = 0; chunk < NCH2; chunk++) {
            const uint32_t cur = sb + (uint32_t)(chunk & 1) * BUF_BYTES;
            const bool hn = (chunk + 1 < NCH2);
            uint2 v0[4], v1[4];
            if (hn) {
                const uint32_t nxt = sb + (uint32_t)((chunk + 1) & 1) * BUF_BYTES;
                b_async(chunk + 1, nxt);
                set_meta(chunk + 1, nxt, (((chunk + 1) & 1) == 0));
                a_load4(0, v0); a_load4(1, v1);
            }
#pragma unroll
            for (int s = 0; s < 8; s++) {
                pass_step(cur, s);
                if (hn && (s & 1)) {
                    const int j = s >> 1;         // 0..3
                    a_finish2(j, v0, v1);
                    if (j < 3) { a_load4(2 * j + 2, v0); a_load4(2 * j + 3, v1); }
                }
            }
            if (hn) CP_WAIT0();
            __syncthreads();
        }

        // epilogue
        float* ob = out + (size_t)b * COUT * HW + p0;
        const int mbase = mw * 64 + (lane >> 2);
        const int nbase2 = nw * 32 + (lane & 3) * 2;
#pragma unroll
        for (int mi = 0; mi < 4; mi++) {
#pragma unroll
            for (int ni = 0; ni < 4; ni++) {
                const int m = mbase + mi * 16;
                const int n = nbase2 + ni * 8;
                ob[(size_t)n * HW + m]           = acc[mi][ni][0];
                ob[(size_t)(n + 1) * HW + m]     = acc[mi][ni][1];
                ob[(size_t)n * HW + m + 8]       = acc[mi][ni][2];
                ob[(size_t)(n + 1) * HW + m + 8] = acc[mi][ni][3];
            }
        }
    }
}

// ---------------------------------------------------------------------------
extern "C" void kernel_launch(void* const* d_in, const int* in_sizes, int n_in,
                              void* d_out, int out_size)
{
    (void)in_sizes; (void)n_in; (void)out_size;
    const float* x      = (const float*)d_in[0];
    const float* w_off  = (const float*)d_in[1];
    const float* b_off  = (const float*)d_in[2];
    const float* w_conv = (const float*)d_in[3];
    float* out = (float*)d_out;

    cudaFuncSetAttribute(fused_kernel,
                         cudaFuncAttributeMaxDynamicSharedMemorySize, SMEM_TOTAL);

    prepack_kernel<<<(NPRE1 + NPRE2 + 255) / 256, 256>>>(w_conv, w_off, x);
    fused_kernel<<<128, 512, SMEM_TOTAL>>>(b_off, out);
}

// round 15
// speedup vs baseline: 1.0233x; 1.0071x over previous
#include <cuda_runtime.h>
#include <cuda_bf16.h>
#include <cuda_fp16.h>
#include <cstdint>

// Problem constants
#define BATCH 4
#define CIN   256
#define CQUAD 64          // CIN/4 channel-quads
#define COUT  256
#define HH    64
#define WW    64
#define HW    4096
#define NTAP  9
#define KTOT  2304        // tap-major: k = tap*256 + c
#define NCH2  18          // phase-2 chunks: 9 taps * 2 chunks of 128 channels

// ---------------- scratch ----------------
__device__ int4     g_idx[BATCH * NTAP * HW];
__device__ float4   g_wt [BATCH * NTAP * HW];
__device__ __half   g_bf[COUT * KTOT];          // w_conv fp16 [n][k]
__device__ __half   g_of[32 * KTOT];            // w_off fp16 [n(27->32)][k]
__device__ uint2    g_x4[BATCH * CQUAD * HW];   // x as 4-channel fp16 quads [b][c4][p]

// ---------------- helpers ----------------
__device__ __forceinline__ uint32_t smem_u32(const void* p) {
    uint32_t a;
    asm("{ .reg .u64 t; cvta.to.shared.u64 t, %1; cvt.u32.u64 %0, t; }" : "=r"(a) : "l"(p));
    return a;
}
__device__ __forceinline__ void ldm_x4(uint32_t* r, uint32_t addr) {
    asm volatile("ldmatrix.sync.aligned.m8n8.x4.shared.b16 {%0,%1,%2,%3}, [%4];"
                 : "=r"(r[0]), "=r"(r[1]), "=r"(r[2]), "=r"(r[3]) : "r"(addr));
}
__device__ __forceinline__ void mma_fp16(float* c, const uint32_t* a, const uint32_t* b) {
    asm volatile(
        "mma.sync.aligned.m16n8k16.row.col.f32.f16.f16.f32 "
        "{%0,%1,%2,%3}, {%4,%5,%6,%7}, {%8,%9}, {%0,%1,%2,%3};"
        : "+f"(c[0]), "+f"(c[1]), "+f"(c[2]), "+f"(c[3])
        : "r"(a[0]), "r"(a[1]), "r"(a[2]), "r"(a[3]), "r"(b[0]), "r"(b[1]));
}
__device__ __forceinline__ void cpasync16(uint32_t dst, const void* src) {
    asm volatile("cp.async.cg.shared.global [%0], [%1], 16;" :: "r"(dst), "l"(src));
}
#define CP_COMMIT() asm volatile("cp.async.commit_group;")
#define CP_WAIT0()  asm volatile("cp.async.wait_group 0;" ::: "memory")

__device__ __forceinline__ uint32_t pack_f16x2_single(float v0, float v1) {
    const __half h0 = __float2half_rn(v0);
    const __half h1 = __float2half_rn(v1);
    return (uint32_t)__half_as_ushort(h0) | ((uint32_t)__half_as_ushort(h1) << 16);
}
__device__ __forceinline__ void sts128(uint32_t addr, uint32_t r0, uint32_t r1,
                                       uint32_t r2, uint32_t r3) {
    asm volatile("st.shared.v4.b32 [%0], {%1, %2, %3, %4};"
                 :: "r"(addr), "r"(r0), "r"(r1), "r"(r2), "r"(r3) : "memory");
}

// ---------------------------------------------------------------------------
// Stage 0 (merged): prepack weights (fp16, tap-major) + x (fp16 channel quads)
// ---------------------------------------------------------------------------
#define NPRE1 ((COUT + 32) * KTOT)            // 663552
#define NPRE2 (BATCH * CQUAD * HW)            // 1048576

__global__ __launch_bounds__(256)
void prepack_kernel(const float* __restrict__ w_conv,
                    const float* __restrict__ w_off,
                    const float* __restrict__ x)
{
    const int i = blockIdx.x * 256 + threadIdx.x;
    if (i < COUT * KTOT) {
        const int n = i / KTOT, k = i % KTOT;
        const int tap = k >> 8, c = k & 255;
        g_bf[i] = __float2half_rn(w_conv[(n * CIN + c) * 9 + tap]);
    } else if (i < NPRE1) {
        const int j = i - COUT * KTOT;
        const int n = j / KTOT, k = j % KTOT;
        const int tap = k >> 8, c = k & 255;
        g_of[j] = __float2half_rn((n < 27) ? w_off[(n * CIN + c) * 9 + tap] : 0.f);
    } else {
        const int j = i - NPRE1;
        if (j < NPRE2) {
            const int b  = j >> 18;           // / (CQUAD*HW)
            const int r  = j & 262143;
            const int c4 = r >> 12;
            const int p  = r & 4095;
            const float* xp = x + ((size_t)b * CIN + 4 * c4) * HW + p;
            uint2 q;
            q.x = pack_f16x2_single(xp[0], xp[HW]);
            q.y = pack_f16x2_single(xp[2 * HW], xp[3 * HW]);
            g_x4[j] = q;
        }
    }
}

// ---------------------------------------------------------------------------
// Fused kernel: 128 CTAs x 512 threads, CTA = 128 pixels x 256 n.
// Phase 1 = offset conv (fp16 mma, N=32), 9 chunks of 256 channels (1 tap).
// Phase 2 = main GEMM (N=256), 18 chunks of 128 channels, double-buffered.
// sacc parked at top of smem so phase-2 chunk-0 B prefetch overlaps the
// phase-1 epilogue; epilogue distributed across all 512 threads.
// ---------------------------------------------------------------------------
// Phase-1 smem (K=256 chunks)
#define OROWB  528
#define OS_A   0
#define OS_B   (128 * OROWB)                  // 67584
#define OBUF   (OS_B + 32 * OROWB)            // 84480 (x2 = 168960)
// Phase-2 smem (K=128 chunks)
#define ROWB   272
#define SM_A   0
#define SM_B   (128 * ROWB)                   // 34816
#define BUF_BYTES (SM_B + 256 * ROWB)         // 104448
#define SMEM_TOTAL (2 * BUF_BYTES)            // 208896
// sacc: 128*33*4 = 16896 bytes at top of smem
#define OS_ACC (SMEM_TOTAL - 16896)           // 192000

__global__ __launch_bounds__(512, 1)
void fused_kernel(const float* __restrict__ b_off,
                  float* __restrict__ out)
{
    extern __shared__ char smem[];
    const uint32_t sb = smem_u32(smem);
    const int t    = threadIdx.x;
    const int lane = t & 31;
    const int wid  = t >> 5;
    const int b    = blockIdx.x >> 5;
    const int p0   = (blockIdx.x & 31) * 128;

    const uint2* xqb = g_x4 + (size_t)b * CQUAD * HW;

    const int am = t & 127;   // pixel
    const int aq = t >> 7;    // channel quarter

    //============== PHASE 1: offset conv (9 chunks x 256 ch) ==============
    {
        const int ph = (p0 + am) >> 6;
        const int pw = (p0 + am) & 63;

        const int mw = wid & 7;
        const int nw = wid >> 3;

        const uint32_t a_row  = (uint32_t)(mw * 16 + (lane & 15));
        const uint32_t a_colb = (uint32_t)((lane >> 4) * 16);
        const uint32_t b_row  = (uint32_t)(nw * 16 + (lane & 7) + ((lane >> 4) << 3));
        const uint32_t b_colb = (uint32_t)(((lane >> 3) & 1) * 16);

        float acc[2][4];
#pragma unroll
        for (int ni = 0; ni < 2; ni++)
#pragma unroll
            for (int j = 0; j < 4; j++) acc[ni][j] = 0.f;

        const uint2* xcn = xqb;
        bool okn = false;
        uint32_t nbase = sb;

        // each thread owns 64 channels = 16 quads of the 256-ch chunk
        auto set_meta = [&](int tap, uint32_t base) {
            const int yy = ph - 1 + tap / 3;
            const int xx = pw - 1 + tap % 3;
            okn = (yy >= 0) && (yy < HH) && (xx >= 0) && (xx < WW);
            xcn = xqb + (size_t)(aq * 16) * HW + (okn ? (yy * WW + xx) : 0);
            nbase = base;
        };
        auto a_load1 = [&](int g, uint2* v) {
            if (okn) *v = __ldg(xcn + (size_t)g * HW);
            else     *v = make_uint2(0u, 0u);
        };
        auto a_finish2 = [&](int j, const uint2* v0, const uint2* v1) {
            const uint32_t colb = (uint32_t)(128 * aq + 16 * j);
            sts128(nbase + OS_A + (uint32_t)am * OROWB + colb,
                   v0->x, v0->y, v1->x, v1->y);
        };
        auto b_async = [&](int tap, uint32_t base) {
            const int n = t >> 4, vw = t & 15;
            const size_t gofs = (size_t)n * KTOT + tap * 256 + vw * 8;
            const uint32_t bo = (uint32_t)(n * OROWB + vw * 16);
            cpasync16(base + OS_B + bo, g_of + gofs);
            cpasync16(base + OS_B + bo + 256, g_of + gofs + 128);
            CP_COMMIT();
        };
        auto pass_step = [&](uint32_t base, int s) {
            uint32_t bf[2][2];
            {
                uint32_t r[4];
                ldm_x4(r, base + OS_B + b_row * OROWB + b_colb + s * 32);
                bf[0][0] = r[0]; bf[0][1] = r[1];
                bf[1][0] = r[2]; bf[1][1] = r[3];
            }
            uint32_t af[4];
            ldm_x4(af, base + OS_A + a_row * OROWB + a_colb + s * 32);
#pragma unroll
            for (int ni = 0; ni < 2; ni++)
                mma_fp16(acc[ni], af, bf[ni]);
        };

        // prologue: build chunk 0 (tap 0)
        b_async(0, sb);
        set_meta(0, sb);
        {
            uint2 u0, u1;
#pragma unroll
            for (int j = 0; j < 8; j++) {
                a_load1(2 * j, &u0); a_load1(2 * j + 1, &u1);
                a_finish2(j, &u0, &u1);
            }
        }
        CP_WAIT0();
        __syncthreads();

        for (int chunk = 0; chunk < NTAP; chunk++) {
            const uint32_t cur = sb + (uint32_t)(chunk & 1) * OBUF;
            const bool hn = (chunk + 1 < NTAP);
            uint2 v0, v1;
            if (hn) {
                const uint32_t nxt = sb + (uint32_t)((chunk + 1) & 1) * OBUF;
                b_async(chunk + 1, nxt);
                set_meta(chunk + 1, nxt);
                a_load1(0, &v0); a_load1(1, &v1);
            }
#pragma unroll
            for (int s = 0; s < 16; s++) {
                pass_step(cur, s);
                if (hn && (s & 1)) {
                    const int j = s >> 1;         // 0..7
                    a_finish2(j, &v0, &v1);
                    if (j < 7) { a_load1(2 * j + 2, &v0); a_load1(2 * j + 3, &v1); }
                }
            }
            if (hn) CP_WAIT0();
            __syncthreads();
        }

        // stash acc so any thread can read any pixel's 27 outputs
        float* sacc = reinterpret_cast<float*>(smem + OS_ACC);
        const int mb = mw * 16 + (lane >> 2);
        const int nb = nw * 16 + (lane & 3) * 2;
#pragma unroll
        for (int ni = 0; ni < 2; ni++) {
            const int n = nb + ni * 8;
            sacc[mb * 33 + n]           = acc[ni][0];
            sacc[mb * 33 + n + 1]       = acc[ni][1];
            sacc[(mb + 8) * 33 + n]     = acc[ni][2];
            sacc[(mb + 8) * 33 + n + 1] = acc[ni][3];
        }
        __syncthreads();

        // --- early phase-2 chunk-0 B prefetch (buffers 0..168960 now free) ---
        {
#pragma unroll
            for (int q2 = 0; q2 < 8; q2++) {
                const int v2 = t + 512 * q2;
                const int n = v2 >> 4, vw = v2 & 15;
                const size_t gofs = (size_t)n * KTOT + vw * 8;   // tap 0, c0 = 0
                cpasync16(sb + SM_B + (uint32_t)(n * ROWB + vw * 16), g_bf + gofs);
            }
            CP_COMMIT();
        }

        // --- meta epilogue: 1152 (tap, pixel) items over all 512 threads ---
        for (int it = t; it < NTAP * 128; it += 512) {
            const int k  = it >> 7;
            const int pl = it & 127;
            const int p  = p0 + pl;
            const int h  = p >> 6, w = p & 63;
            const float* row = sacc + pl * 33;

            const float dy = row[2 * k]     + __ldg(b_off + 2 * k);
            const float dx = row[2 * k + 1] + __ldg(b_off + 2 * k + 1);
            const float mz = row[18 + k]    + __ldg(b_off + 18 + k);
            const float m  = 1.f / (1.f + expf(-mz));

            const float py = dy + (float)(h - 1 + k / 3);
            const float px = dx + (float)(w - 1 + k % 3);
            const float y0 = floorf(py);
            const float x0 = floorf(px);
            const float wy = py - y0;
            const float wx = px - x0;

            const float cy[2]  = { y0, y0 + 1.f };
            const float cx[2]  = { x0, x0 + 1.f };
            const float wyv[2] = { 1.f - wy, wy };
            const float wxv[2] = { 1.f - wx, wx };

            int   idxv[4];
            float wtv[4];
#pragma unroll
            for (int jy = 0; jy < 2; jy++) {
#pragma unroll
                for (int jx = 0; jx < 2; jx++) {
                    const float yc = cy[jy], xc = cx[jx];
                    const bool valid = (yc >= 0.f) && (yc <= (float)(HH - 1)) &&
                                       (xc >= 0.f) && (xc <= (float)(WW - 1));
                    const int yi = (int)fminf(fmaxf(yc, 0.f), (float)(HH - 1));
                    const int xi = (int)fminf(fmaxf(xc, 0.f), (float)(WW - 1));
                    const int j = jy * 2 + jx;
                    idxv[j] = yi * WW + xi;
                    wtv[j]  = valid ? (wyv[jy] * wxv[jx] * m) : 0.f;
                }
            }
            const int o = (b * NTAP + k) * HW + p;
            g_idx[o] = make_int4(idxv[0], idxv[1], idxv[2], idxv[3]);
            g_wt[o]  = make_float4(wtv[0], wtv[1], wtv[2], wtv[3]);
        }
    }
    __syncthreads();   // meta visible (block-wide) + phase-1 smem free

    //======================= PHASE 2: main GEMM =======================
    {
        const int mw = wid & 1;
        const int nw = wid >> 1;

        float acc[4][4][4];
#pragma unroll
        for (int mi = 0; mi < 4; mi++)
#pragma unroll
            for (int ni = 0; ni < 4; ni++)
#pragma unroll
                for (int j = 0; j < 4; j++) acc[mi][ni][j] = 0.f;

        const uint32_t a_row  = (uint32_t)(mw * 64 + (lane & 15));
        const uint32_t a_colb = (uint32_t)((lane >> 4) * 16);
        const uint32_t b_row  = (uint32_t)(nw * 32 + (lane & 7) + ((lane >> 4) << 3));
        const uint32_t b_colb = (uint32_t)(((lane >> 3) & 1) * 16);

        int4   idn;
        float4 wtn;
        const uint2* xcn = xqb;
        uint32_t nbase = sb;

        auto set_meta = [&](int chunk, uint32_t base, bool reload) {
            const int tap = chunk >> 1;
            const int cg0 = (chunk & 1) * 32;
            if (reload) {
                const int off = (b * NTAP + tap) * HW + p0 + am;
                idn = g_idx[off];
                wtn = g_wt[off];
            }
            xcn = xqb + (size_t)(cg0 + aq * 8) * HW;
            nbase = base;
        };
        auto a_load4 = [&](int g, uint2* v) {
            const uint2* xp = xcn + (size_t)g * HW;
            v[0] = __ldg(xp + idn.x); v[1] = __ldg(xp + idn.y);
            v[2] = __ldg(xp + idn.z); v[3] = __ldg(xp + idn.w);
        };
        auto dotpack2 = [&](const uint2* v, uint32_t* o) {
            const float2 f0a = __half22float2(*reinterpret_cast<const __half2*>(&v[0].x));
            const float2 f1a = __half22float2(*reinterpret_cast<const __half2*>(&v[1].x));
            const float2 f2a = __half22float2(*reinterpret_cast<const __half2*>(&v[2].x));
            const float2 f3a = __half22float2(*reinterpret_cast<const __half2*>(&v[3].x));
            const float a0 = wtn.x * f0a.x + wtn.y * f1a.x + wtn.z * f2a.x + wtn.w * f3a.x;
            const float a1 = wtn.x * f0a.y + wtn.y * f1a.y + wtn.z * f2a.y + wtn.w * f3a.y;
            o[0] = pack_f16x2_single(a0, a1);
            const float2 f0b = __half22float2(*reinterpret_cast<const __half2*>(&v[0].y));
            const float2 f1b = __half22float2(*reinterpret_cast<const __half2*>(&v[1].y));
            const float2 f2b = __half22float2(*reinterpret_cast<const __half2*>(&v[2].y));
            const float2 f3b = __half22float2(*reinterpret_cast<const __half2*>(&v[3].y));
            const float a2 = wtn.x * f0b.x + wtn.y * f1b.x + wtn.z * f2b.x + wtn.w * f3b.x;
            const float a3 = wtn.x * f0b.y + wtn.y * f1b.y + wtn.z * f2b.y + wtn.w * f3b.y;
            o[1] = pack_f16x2_single(a2, a3);
        };
        auto a_finish2 = [&](int j, const uint2* v0, const uint2* v1) {
            uint32_t w0[2], w1[2];
            dotpack2(v0, w0);
            dotpack2(v1, w1);
            const uint32_t colb = (uint32_t)(64 * aq + 16 * j);
            sts128(nbase + SM_A + (uint32_t)am * ROWB + colb,
                   w0[0], w0[1], w1[0], w1[1]);
        };
        auto b_async = [&](int chunk, uint32_t base) {
            const int tap = chunk >> 1;
            const int c0  = (chunk & 1) * 128;
#pragma unroll
            for (int q2 = 0; q2 < 8; q2++) {
                const int v2 = t + 512 * q2;
                const int n = v2 >> 4, vw = v2 & 15;
                const size_t gofs = (size_t)n * KTOT + tap * 256 + c0 + vw * 8;
                cpasync16(base + SM_B + (uint32_t)(n * ROWB + vw * 16), g_bf + gofs);
            }
            CP_COMMIT();
        };
        auto pass_step = [&](uint32_t base, int s) {
            const uint32_t A = base + SM_A;
            const uint32_t B = base + SM_B;
            uint32_t bf[4][2];
#pragma unroll
            for (int np = 0; np < 2; np++) {
                uint32_t r[4];
                ldm_x4(r, B + (b_row + np * 16) * ROWB + b_colb + s * 32);
                bf[np * 2][0] = r[0]; bf[np * 2][1] = r[1];
                bf[np * 2 + 1][0] = r[2]; bf[np * 2 + 1][1] = r[3];
            }
#pragma unroll
            for (int mi = 0; mi < 4; mi++) {
                uint32_t af[4];
                ldm_x4(af, A + (a_row + mi * 16) * ROWB + a_colb + s * 32);
#pragma unroll
                for (int ni = 0; ni < 4; ni++)
                    mma_fp16(acc[mi][ni], af, bf[ni]);
            }
        };

        // prologue (chunk-0 B already in flight from phase-1 tail)
        set_meta(0, sb, true);
        {
            uint2 u0[4], u1[4];
#pragma unroll
            for (int j = 0; j < 4; j++) {
                a_load4(2 * j, u0); a_load4(2 * j + 1, u1);
                a_finish2(j, u0, u1);
            }
        }
        CP_WAIT0();
        __syncthreads();

        for (int chunk = 0; chunk < NCH2; chunk++) {
            const uint32_t cur = sb + (uint32_t)(chunk & 1) * BUF_BYTES;
            const bool hn = (chunk + 1 < NCH2);
            uint2 v0[4], v1[4];
            if (hn) {
                const uint32_t nxt = sb + (uint32_t)((chunk + 1) & 1) * BUF_BYTES;
                b_async(chunk + 1, nxt);
                set_meta(chunk + 1, nxt, (((chunk + 1) & 1) == 0));
                a_load4(0, v0); a_load4(1, v1);
            }
#pragma unroll
            for (int s = 0; s < 8; s++) {
                pass_step(cur, s);
                if (hn && (s & 1)) {
                    const int j = s >> 1;         // 0..3
                    a_finish2(j, v0, v1);
                    if (j < 3) { a_load4(2 * j + 2, v0); a_load4(2 * j + 3, v1); }
                }
            }
            if (hn) CP_WAIT0();
            __syncthreads();
        }

        // epilogue
        float* ob = out + (size_t)b * COUT * HW + p0;
        const int mbase = mw * 64 + (lane >> 2);
        const int nbase2 = nw * 32 + (lane & 3) * 2;
#pragma unroll
        for (int mi = 0; mi < 4; mi++) {
#pragma unroll
            for (int ni = 0; ni < 4; ni++) {
                const int m = mbase + mi * 16;
                const int n = nbase2 + ni * 8;
                ob[(size_t)n * HW + m]           = acc[mi][ni][0];
                ob[(size_t)(n + 1) * HW + m]     = acc[mi][ni][1];
                ob[(size_t)n * HW + m + 8]       = acc[mi][ni][2];
                ob[(size_t)(n + 1) * HW + m + 8] = acc[mi][ni][3];
            }
        }
    }
}

// ---------------------------------------------------------------------------
extern "C" void kernel_launch(void* const* d_in, const int* in_sizes, int n_in,
                              void* d_out, int out_size)
{
    (void)in_sizes; (void)n_in; (void)out_size;
    const float* x      = (const float*)d_in[0];
    const float* w_off  = (const float*)d_in[1];
    const float* b_off  = (const float*)d_in[2];
    const float* w_conv = (const float*)d_in[3];
    float* out = (float*)d_out;

    cudaFuncSetAttribute(fused_kernel,
                         cudaFuncAttributeMaxDynamicSharedMemorySize, SMEM_TOTAL);

    prepack_kernel<<<(NPRE1 + NPRE2 + 255) / 256, 256>>>(w_conv, w_off, x);
    fused_kernel<<<128, 512, SMEM_TOTAL>>>(b_off, out);
}

// round 16
// speedup vs baseline: 1.0361x; 1.0125x over previous
#include <cuda_runtime.h>
#include <cuda_bf16.h>
#include <cuda_fp16.h>
#include <cstdint>

// Problem constants
#define BATCH 4
#define CIN   256
#define CQUAD 64          // CIN/4 channel-quads
#define COUT  256
#define HH    64
#define WW    64
#define HW    4096
#define NTAP  9
#define KTOT  2304        // tap-major: k = tap*256 + c
#define NCH2  18          // phase-2 chunks: 9 taps * 2 chunks of 128 channels

// ---------------- scratch ----------------
__device__ int4     g_idx[BATCH * NTAP * HW];
__device__ float4   g_wt [BATCH * NTAP * HW];
__device__ __half   g_bf[COUT * KTOT];          // w_conv fp16 [n][k]
__device__ __half   g_of[32 * KTOT];            // w_off fp16 [n(27->32)][k]
__device__ uint2    g_x4[BATCH * CQUAD * HW];   // x as 4-channel fp16 quads [b][c4][p]

// ---------------- helpers ----------------
__device__ __forceinline__ uint32_t smem_u32(const void* p) {
    uint32_t a;
    asm("{ .reg .u64 t; cvta.to.shared.u64 t, %1; cvt.u32.u64 %0, t; }" : "=r"(a) : "l"(p));
    return a;
}
__device__ __forceinline__ void ldm_x4(uint32_t* r, uint32_t addr) {
    asm volatile("ldmatrix.sync.aligned.m8n8.x4.shared.b16 {%0,%1,%2,%3}, [%4];"
                 : "=r"(r[0]), "=r"(r[1]), "=r"(r[2]), "=r"(r[3]) : "r"(addr));
}
__device__ __forceinline__ void mma_fp16(float* c, const uint32_t* a, const uint32_t* b) {
    asm volatile(
        "mma.sync.aligned.m16n8k16.row.col.f32.f16.f16.f32 "
        "{%0,%1,%2,%3}, {%4,%5,%6,%7}, {%8,%9}, {%0,%1,%2,%3};"
        : "+f"(c[0]), "+f"(c[1]), "+f"(c[2]), "+f"(c[3])
        : "r"(a[0]), "r"(a[1]), "r"(a[2]), "r"(a[3]), "r"(b[0]), "r"(b[1]));
}
__device__ __forceinline__ void cpasync16(uint32_t dst, const void* src) {
    asm volatile("cp.async.cg.shared.global [%0], [%1], 16;" :: "r"(dst), "l"(src));
}
#define CP_COMMIT() asm volatile("cp.async.commit_group;")
#define CP_WAIT0()  asm volatile("cp.async.wait_group 0;" ::: "memory")

__device__ __forceinline__ uint32_t pack_f16x2_single(float v0, float v1) {
    const __half h0 = __float2half_rn(v0);
    const __half h1 = __float2half_rn(v1);
    return (uint32_t)__half_as_ushort(h0) | ((uint32_t)__half_as_ushort(h1) << 16);
}
__device__ __forceinline__ void sts128(uint32_t addr, uint32_t r0, uint32_t r1,
                                       uint32_t r2, uint32_t r3) {
    asm volatile("st.shared.v4.b32 [%0], {%1, %2, %3, %4};"
                 :: "r"(addr), "r"(r0), "r"(r1), "r"(r2), "r"(r3) : "memory");
}

// ---------------------------------------------------------------------------
// Stage 0 (merged): prepack weights (fp16, tap-major) + x (fp16 channel quads)
// ---------------------------------------------------------------------------
#define NPRE1 ((COUT + 32) * KTOT)            // 663552
#define NPRE2 (BATCH * CQUAD * HW)            // 1048576

__global__ __launch_bounds__(256)
void prepack_kernel(const float* __restrict__ w_conv,
                    const float* __restrict__ w_off,
                    const float* __restrict__ x)
{
    const int i = blockIdx.x * 256 + threadIdx.x;
    if (i < COUT * KTOT) {
        const int n = i / KTOT, k = i % KTOT;
        const int tap = k >> 8, c = k & 255;
        g_bf[i] = __float2half_rn(w_conv[(n * CIN + c) * 9 + tap]);
    } else if (i < NPRE1) {
        const int j = i - COUT * KTOT;
        const int n = j / KTOT, k = j % KTOT;
        const int tap = k >> 8, c = k & 255;
        g_of[j] = __float2half_rn((n < 27) ? w_off[(n * CIN + c) * 9 + tap] : 0.f);
    } else {
        const int j = i - NPRE1;
        if (j < NPRE2) {
            const int b  = j >> 18;           // / (CQUAD*HW)
            const int r  = j & 262143;
            const int c4 = r >> 12;
            const int p  = r & 4095;
            const float* xp = x + ((size_t)b * CIN + 4 * c4) * HW + p;
            uint2 q;
            q.x = pack_f16x2_single(xp[0], xp[HW]);
            q.y = pack_f16x2_single(xp[2 * HW], xp[3 * HW]);
            g_x4[j] = q;
        }
    }
}

// ---------------------------------------------------------------------------
// Fused kernel: 128 CTAs x 512 threads, CTA = 128 pixels x 256 n.
// Phase 1 = offset conv (fp16 mma, N=32), 9 chunks of 256 channels (1 tap).
// Phase 2 = main GEMM (N=256), 18 chunks of 128 channels, double-buffered,
//           with fragment-level software pipelining (af double-buffer).
// ---------------------------------------------------------------------------
// Phase-1 smem (K=256 chunks)
#define OROWB  528
#define OS_A   0
#define OS_B   (128 * OROWB)                  // 67584
#define OBUF   (OS_B + 32 * OROWB)            // 84480 (x2 = 168960)
// Phase-2 smem (K=128 chunks)
#define ROWB   272
#define SM_A   0
#define SM_B   (128 * ROWB)                   // 34816
#define BUF_BYTES (SM_B + 256 * ROWB)         // 104448
#define SMEM_TOTAL (2 * BUF_BYTES)            // 208896
// sacc: 128*33*4 = 16896 bytes at top of smem
#define OS_ACC (SMEM_TOTAL - 16896)           // 192000

__global__ __launch_bounds__(512, 1)
void fused_kernel(const float* __restrict__ b_off,
                  float* __restrict__ out)
{
    extern __shared__ char smem[];
    const uint32_t sb = smem_u32(smem);
    const int t    = threadIdx.x;
    const int lane = t & 31;
    const int wid  = t >> 5;
    const int b    = blockIdx.x >> 5;
    const int p0   = (blockIdx.x & 31) * 128;

    const uint2* xqb = g_x4 + (size_t)b * CQUAD * HW;

    const int am = t & 127;   // pixel
    const int aq = t >> 7;    // channel quarter

    //============== PHASE 1: offset conv (9 chunks x 256 ch) ==============
    {
        const int ph = (p0 + am) >> 6;
        const int pw = (p0 + am) & 63;

        const int mw = wid & 7;
        const int nw = wid >> 3;

        const uint32_t a_row  = (uint32_t)(mw * 16 + (lane & 15));
        const uint32_t a_colb = (uint32_t)((lane >> 4) * 16);
        const uint32_t b_row  = (uint32_t)(nw * 16 + (lane & 7) + ((lane >> 4) << 3));
        const uint32_t b_colb = (uint32_t)(((lane >> 3) & 1) * 16);

        float acc[2][4];
#pragma unroll
        for (int ni = 0; ni < 2; ni++)
#pragma unroll
            for (int j = 0; j < 4; j++) acc[ni][j] = 0.f;

        const uint2* xcn = xqb;
        bool okn = false;
        uint32_t nbase = sb;

        auto set_meta = [&](int tap, uint32_t base) {
            const int yy = ph - 1 + tap / 3;
            const int xx = pw - 1 + tap % 3;
            okn = (yy >= 0) && (yy < HH) && (xx >= 0) && (xx < WW);
            xcn = xqb + (size_t)(aq * 16) * HW + (okn ? (yy * WW + xx) : 0);
            nbase = base;
        };
        auto a_load1 = [&](int g, uint2* v) {
            if (okn) *v = __ldg(xcn + (size_t)g * HW);
            else     *v = make_uint2(0u, 0u);
        };
        auto a_finish2 = [&](int j, const uint2* v0, const uint2* v1) {
            const uint32_t colb = (uint32_t)(128 * aq + 16 * j);
            sts128(nbase + OS_A + (uint32_t)am * OROWB + colb,
                   v0->x, v0->y, v1->x, v1->y);
        };
        auto b_async = [&](int tap, uint32_t base) {
            const int n = t >> 4, vw = t & 15;
            const size_t gofs = (size_t)n * KTOT + tap * 256 + vw * 8;
            const uint32_t bo = (uint32_t)(n * OROWB + vw * 16);
            cpasync16(base + OS_B + bo, g_of + gofs);
            cpasync16(base + OS_B + bo + 256, g_of + gofs + 128);
            CP_COMMIT();
        };
        auto pass_step = [&](uint32_t base, int s) {
            uint32_t bf[2][2];
            {
                uint32_t r[4];
                ldm_x4(r, base + OS_B + b_row * OROWB + b_colb + s * 32);
                bf[0][0] = r[0]; bf[0][1] = r[1];
                bf[1][0] = r[2]; bf[1][1] = r[3];
            }
            uint32_t af[4];
            ldm_x4(af, base + OS_A + a_row * OROWB + a_colb + s * 32);
#pragma unroll
            for (int ni = 0; ni < 2; ni++)
                mma_fp16(acc[ni], af, bf[ni]);
        };

        // prologue: build chunk 0 (tap 0)
        b_async(0, sb);
        set_meta(0, sb);
        {
            uint2 u0, u1;
#pragma unroll
            for (int j = 0; j < 8; j++) {
                a_load1(2 * j, &u0); a_load1(2 * j + 1, &u1);
                a_finish2(j, &u0, &u1);
            }
        }
        CP_WAIT0();
        __syncthreads();

        for (int chunk = 0; chunk < NTAP; chunk++) {
            const uint32_t cur = sb + (uint32_t)(chunk & 1) * OBUF;
            const bool hn = (chunk + 1 < NTAP);
            uint2 v0, v1;
            if (hn) {
                const uint32_t nxt = sb + (uint32_t)((chunk + 1) & 1) * OBUF;
                b_async(chunk + 1, nxt);
                set_meta(chunk + 1, nxt);
                a_load1(0, &v0); a_load1(1, &v1);
            }
#pragma unroll
            for (int s = 0; s < 16; s++) {
                pass_step(cur, s);
                if (hn && (s & 1)) {
                    const int j = s >> 1;         // 0..7
                    a_finish2(j, &v0, &v1);
                    if (j < 7) { a_load1(2 * j + 2, &v0); a_load1(2 * j + 3, &v1); }
                }
            }
            if (hn) CP_WAIT0();
            __syncthreads();
        }

        // stash acc so any thread can read any pixel's 27 outputs
        float* sacc = reinterpret_cast<float*>(smem + OS_ACC);
        const int mb = mw * 16 + (lane >> 2);
        const int nb = nw * 16 + (lane & 3) * 2;
#pragma unroll
        for (int ni = 0; ni < 2; ni++) {
            const int n = nb + ni * 8;
            sacc[mb * 33 + n]           = acc[ni][0];
            sacc[mb * 33 + n + 1]       = acc[ni][1];
            sacc[(mb + 8) * 33 + n]     = acc[ni][2];
            sacc[(mb + 8) * 33 + n + 1] = acc[ni][3];
        }
        __syncthreads();

        // --- early phase-2 chunk-0 B prefetch (buffers now free) ---
        {
#pragma unroll
            for (int q2 = 0; q2 < 8; q2++) {
                const int v2 = t + 512 * q2;
                const int n = v2 >> 4, vw = v2 & 15;
                const size_t gofs = (size_t)n * KTOT + vw * 8;   // tap 0, c0 = 0
                cpasync16(sb + SM_B + (uint32_t)(n * ROWB + vw * 16), g_bf + gofs);
            }
            CP_COMMIT();
        }

        // --- meta epilogue: 1152 (tap, pixel) items over all 512 threads ---
        for (int it = t; it < NTAP * 128; it += 512) {
            const int k  = it >> 7;
            const int pl = it & 127;
            const int p  = p0 + pl;
            const int h  = p >> 6, w = p & 63;
            const float* row = sacc + pl * 33;

            const float dy = row[2 * k]     + __ldg(b_off + 2 * k);
            const float dx = row[2 * k + 1] + __ldg(b_off + 2 * k + 1);
            const float mz = row[18 + k]    + __ldg(b_off + 18 + k);
            const float m  = 1.f / (1.f + expf(-mz));

            const float py = dy + (float)(h - 1 + k / 3);
            const float px = dx + (float)(w - 1 + k % 3);
            const float y0 = floorf(py);
            const float x0 = floorf(px);
            const float wy = py - y0;
            const float wx = px - x0;

            const float cy[2]  = { y0, y0 + 1.f };
            const float cx[2]  = { x0, x0 + 1.f };
            const float wyv[2] = { 1.f - wy, wy };
            const float wxv[2] = { 1.f - wx, wx };

            int   idxv[4];
            float wtv[4];
#pragma unroll
            for (int jy = 0; jy < 2; jy++) {
#pragma unroll
                for (int jx = 0; jx < 2; jx++) {
                    const float yc = cy[jy], xc = cx[jx];
                    const bool valid = (yc >= 0.f) && (yc <= (float)(HH - 1)) &&
                                       (xc >= 0.f) && (xc <= (float)(WW - 1));
                    const int yi = (int)fminf(fmaxf(yc, 0.f), (float)(HH - 1));
                    const int xi = (int)fminf(fmaxf(xc, 0.f), (float)(WW - 1));
                    const int j = jy * 2 + jx;
                    idxv[j] = yi * WW + xi;
                    wtv[j]  = valid ? (wyv[jy] * wxv[jx] * m) : 0.f;
                }
            }
            const int o = (b * NTAP + k) * HW + p;
            g_idx[o] = make_int4(idxv[0], idxv[1], idxv[2], idxv[3]);
            g_wt[o]  = make_float4(wtv[0], wtv[1], wtv[2], wtv[3]);
        }
    }
    __syncthreads();   // meta visible (block-wide) + phase-1 smem free

    //======================= PHASE 2: main GEMM =======================
    {
        const int mw = wid & 1;
        const int nw = wid >> 1;

        float acc[4][4][4];
#pragma unroll
        for (int mi = 0; mi < 4; mi++)
#pragma unroll
            for (int ni = 0; ni < 4; ni++)
#pragma unroll
                for (int j = 0; j < 4; j++) acc[mi][ni][j] = 0.f;

        const uint32_t a_row  = (uint32_t)(mw * 64 + (lane & 15));
        const uint32_t a_colb = (uint32_t)((lane >> 4) * 16);
        const uint32_t b_row  = (uint32_t)(nw * 32 + (lane & 7) + ((lane >> 4) << 3));
        const uint32_t b_colb = (uint32_t)(((lane >> 3) & 1) * 16);

        int4   idn;
        float4 wtn;
        const uint2* xcn = xqb;
        uint32_t nbase = sb;

        auto set_meta = [&](int chunk, uint32_t base, bool reload) {
            const int tap = chunk >> 1;
            const int cg0 = (chunk & 1) * 32;
            if (reload) {
                const int off = (b * NTAP + tap) * HW + p0 + am;
                idn = g_idx[off];
                wtn = g_wt[off];
            }
            xcn = xqb + (size_t)(cg0 + aq * 8) * HW;
            nbase = base;
        };
        auto a_load4 = [&](int g, uint2* v) {
            const uint2* xp = xcn + (size_t)g * HW;
            v[0] = __ldg(xp + idn.x); v[1] = __ldg(xp + idn.y);
            v[2] = __ldg(xp + idn.z); v[3] = __ldg(xp + idn.w);
        };
        auto dotpack2 = [&](const uint2* v, uint32_t* o) {
            const float2 f0a = __half22float2(*reinterpret_cast<const __half2*>(&v[0].x));
            const float2 f1a = __half22float2(*reinterpret_cast<const __half2*>(&v[1].x));
            const float2 f2a = __half22float2(*reinterpret_cast<const __half2*>(&v[2].x));
            const float2 f3a = __half22float2(*reinterpret_cast<const __half2*>(&v[3].x));
            const float a0 = wtn.x * f0a.x + wtn.y * f1a.x + wtn.z * f2a.x + wtn.w * f3a.x;
            const float a1 = wtn.x * f0a.y + wtn.y * f1a.y + wtn.z * f2a.y + wtn.w * f3a.y;
            o[0] = pack_f16x2_single(a0, a1);
            const float2 f0b = __half22float2(*reinterpret_cast<const __half2*>(&v[0].y));
            const float2 f1b = __half22float2(*reinterpret_cast<const __half2*>(&v[1].y));
            const float2 f2b = __half22float2(*reinterpret_cast<const __half2*>(&v[2].y));
            const float2 f3b = __half22float2(*reinterpret_cast<const __half2*>(&v[3].y));
            const float a2 = wtn.x * f0b.x + wtn.y * f1b.x + wtn.z * f2b.x + wtn.w * f3b.x;
            const float a3 = wtn.x * f0b.y + wtn.y * f1b.y + wtn.z * f2b.y + wtn.w * f3b.y;
            o[1] = pack_f16x2_single(a2, a3);
        };
        auto a_finish2 = [&](int j, const uint2* v0, const uint2* v1) {
            uint32_t w0[2], w1[2];
            dotpack2(v0, w0);
            dotpack2(v1, w1);
            const uint32_t colb = (uint32_t)(64 * aq + 16 * j);
            sts128(nbase + SM_A + (uint32_t)am * ROWB + colb,
                   w0[0], w0[1], w1[0], w1[1]);
        };
        auto b_async = [&](int chunk, uint32_t base) {
            const int tap = chunk >> 1;
            const int c0  = (chunk & 1) * 128;
#pragma unroll
            for (int q2 = 0; q2 < 8; q2++) {
                const int v2 = t + 512 * q2;
                const int n = v2 >> 4, vw = v2 & 15;
                const size_t gofs = (size_t)n * KTOT + tap * 256 + c0 + vw * 8;
                cpasync16(base + SM_B + (uint32_t)(n * ROWB + vw * 16), g_bf + gofs);
            }
            CP_COMMIT();
        };
        // Fragment-pipelined step: B first (independent batch), then af
        // double-buffered so each af load is covered by 4 MMAs of the
        // previous fragment.
        auto pass_step = [&](uint32_t base, int s) {
            const uint32_t A = base + SM_A;
            const uint32_t B = base + SM_B;
            uint32_t bf[4][2];
#pragma unroll
            for (int np = 0; np < 2; np++) {
                uint32_t r[4];
                ldm_x4(r, B + (b_row + np * 16) * ROWB + b_colb + s * 32);
                bf[np * 2][0] = r[0]; bf[np * 2][1] = r[1];
                bf[np * 2 + 1][0] = r[2]; bf[np * 2 + 1][1] = r[3];
            }
            uint32_t af[2][4];
            ldm_x4(af[0], A + a_row * ROWB + a_colb + s * 32);
#pragma unroll
            for (int mi = 0; mi < 4; mi++) {
                if (mi < 3)
                    ldm_x4(af[(mi + 1) & 1],
                           A + (a_row + (mi + 1) * 16) * ROWB + a_colb + s * 32);
#pragma unroll
                for (int ni = 0; ni < 4; ni++)
                    mma_fp16(acc[mi][ni], af[mi & 1], bf[ni]);
            }
        };

        // prologue (chunk-0 B already in flight from phase-1 tail)
        set_meta(0, sb, true);
        {
            uint2 u0[4], u1[4];
#pragma unroll
            for (int j = 0; j < 4; j++) {
                a_load4(2 * j, u0); a_load4(2 * j + 1, u1);
                a_finish2(j, u0, u1);
            }
        }
        CP_WAIT0();
        __syncthreads();

        for (int chunk = 0; chunk < NCH2; chunk++) {
            const uint32_t cur = sb + (uint32_t)(chunk & 1) * BUF_BYTES;
            const bool hn = (chunk + 1 < NCH2);
            uint2 v0[4], v1[4];
            if (hn) {
                const uint32_t nxt = sb + (uint32_t)((chunk + 1) & 1) * BUF_BYTES;
                b_async(chunk + 1, nxt);
                set_meta(chunk + 1, nxt, (((chunk + 1) & 1) == 0));
                a_load4(0, v0); a_load4(1, v1);
            }
#pragma unroll
            for (int s = 0; s < 8; s++) {
                pass_step(cur, s);
                if (hn && (s & 1)) {
                    const int j = s >> 1;         // 0..3
                    a_finish2(j, v0, v1);
                    if (j < 3) { a_load4(2 * j + 2, v0); a_load4(2 * j + 3, v1); }
                }
            }
            if (hn) CP_WAIT0();
            __syncthreads();
        }

        // epilogue
        float* ob = out + (size_t)b * COUT * HW + p0;
        const int mbase = mw * 64 + (lane >> 2);
        const int nbase2 = nw * 32 + (lane & 3) * 2;
#pragma unroll
        for (int mi = 0; mi < 4; mi++) {
#pragma unroll
            for (int ni = 0; ni < 4; ni++) {
                const int m = mbase + mi * 16;
                const int n = nbase2 + ni * 8;
                ob[(size_t)n * HW + m]           = acc[mi][ni][0];
                ob[(size_t)(n + 1) * HW + m]     = acc[mi][ni][1];
                ob[(size_t)n * HW + m + 8]       = acc[mi][ni][2];
                ob[(size_t)(n + 1) * HW + m + 8] = acc[mi][ni][3];
            }
        }
    }
}

// ---------------------------------------------------------------------------
extern "C" void kernel_launch(void* const* d_in, const int* in_sizes, int n_in,
                              void* d_out, int out_size)
{
    (void)in_sizes; (void)n_in; (void)out_size;
    const float* x      = (const float*)d_in[0];
    const float* w_off  = (const float*)d_in[1];
    const float* b_off  = (const float*)d_in[2];
    const float* w_conv = (const float*)d_in[3];
    float* out = (float*)d_out;

    cudaFuncSetAttribute(fused_kernel,
                         cudaFuncAttributeMaxDynamicSharedMemorySize, SMEM_TOTAL);

    prepack_kernel<<<(NPRE1 + NPRE2 + 255) / 256, 256>>>(w_conv, w_off, x);
    fused_kernel<<<128, 512, SMEM_TOTAL>>>(b_off, out);
}